// round 9
// baseline (speedup 1.0000x reference)
#include <cuda_runtime.h>
#include <math.h>

#define T_STEPS 4096
#define H_DIM   2048
#define O_DIM   512

#define RNN_CTAS    128
#define RNN_THREADS 256

#define SENTINEL 0x7f800001u   // NaN payload; tanh(finite) can never produce it

// ---------------- device scratch (allocation-free rule) ----------------
__device__ float g_xp[(size_t)T_STEPS * H_DIM];   // x @ W_ih^T + b_ih + b_hh
__device__ float g_hs[(size_t)T_STEPS * H_DIM];   // all hidden states h_t

// Morally-strong volatile ops for the data-as-flag protocol (R8, proven).
__device__ __forceinline__ uint4 ld_vol_u4(const uint4* p)
{
    uint4 v;
    asm volatile("ld.volatile.global.v4.u32 {%0,%1,%2,%3}, [%4];"
                 : "=r"(v.x), "=r"(v.y), "=r"(v.z), "=r"(v.w)
                 : "l"(p) : "memory");
    return v;
}
__device__ __forceinline__ void st_vol_f32(float* p, float v)
{
    asm volatile("st.volatile.global.f32 [%0], %1;"
                 :: "l"(p), "f"(v) : "memory");
}
__device__ __forceinline__ bool has_sent(uint4 v)
{
    return (v.x == SENTINEL) | (v.y == SENTINEL) |
           (v.z == SENTINEL) | (v.w == SENTINEL);
}

// packed f32x2 helpers
__device__ __forceinline__ void fma2(unsigned long long& acc,
                                     unsigned long long a, unsigned long long b)
{
    asm("fma.rn.f32x2 %0, %1, %2, %0;" : "+l"(acc) : "l"(a), "l"(b));
}
__device__ __forceinline__ unsigned long long pack2(float lo, float hi)
{
    unsigned long long v;
    asm("mov.b64 %0, {%1, %2};" : "=l"(v) : "f"(lo), "f"(hi));
    return v;
}
__device__ __forceinline__ float2 unpack2(unsigned long long v)
{
    float2 r;
    asm("mov.b64 {%0, %1}, %2;" : "=f"(r.x), "=f"(r.y) : "l"(v));
    return r;
}

// ---------------- sentinel reset (graph-replay safe) -------------------
__global__ void reset_hs_kernel()
{
    size_t i = (size_t)blockIdx.x * blockDim.x + threadIdx.x;
    ((uint4*)g_hs)[i] = make_uint4(SENTINEL, SENTINEL, SENTINEL, SENTINEL);
}

// ---------------- persistent recurrence kernel -------------------------
// h_t = tanh(xp_t + W_hh @ h_{t-1}); k-split layout:
// 128 CTAs x 16 rows; warp w owns k-slice [w*256, w*256+256) for ALL 16 rows
// (lane l: k = w*256 + p*128 + l*4, p in {0,1}) -> per-step LDS traffic is
// 8KB/SM (was 64KB). f32x2 packed FMA halves issue count. Cross-warp combine
// via smem partials; warp w produces output rows 2w, 2w+1.
// Sync: R8's proven data-as-flag volatile protocol, unchanged.
__global__ void __launch_bounds__(RNN_THREADS, 1)
rnn_kernel(const float* __restrict__ W_hh, const float* __restrict__ h0)
{
    __shared__ __align__(16) float hbuf[2][H_DIM];       // double-buffered h
    __shared__ __align__(16) float pbuf[16][RNN_THREADS]; // partials [row][tid]
    const int tid  = threadIdx.x;
    const int lane = tid & 31;
    const int wid  = tid >> 5;                    // 0..7
    const int rowbase = blockIdx.x * 16;

    // Weights: wp[r][p] = 4 floats (2 f32x2) at k = wid*256 + p*128 + lane*4.
    ulonglong2 wp[16][2];   // 128 regs
#pragma unroll
    for (int r = 0; r < 16; r++) {
#pragma unroll
        for (int p = 0; p < 2; p++) {
            const ulonglong2* src = (const ulonglong2*)
                (W_hh + (size_t)(rowbase + r) * H_DIM + wid * 256 + p * 128 + lane * 4);
            wp[r][p] = __ldg(src);
        }
    }

    for (int t = 0; t < T_STEPS; t++) {
        const int buf = t & 1;

        // xp prefetch: warp w outputs rows 2w, 2w+1.
        float xpv0 = 0.f, xpv1 = 0.f;
        if (lane == 0) {
            xpv0 = __ldg(&g_xp[(size_t)t * H_DIM + rowbase + 2 * wid]);
            xpv1 = __ldg(&g_xp[(size_t)t * H_DIM + rowbase + 2 * wid + 1]);
        }

        // Acquire h_{t-1}: spin on the actual words (volatile, morally strong).
        float4 a4, b4;
        if (t == 0) {
            a4 = __ldg(&((const float4*)h0)[tid]);
            b4 = __ldg(&((const float4*)h0)[tid + RNN_THREADS]);
        } else {
            const uint4* hp = (const uint4*)(g_hs + (size_t)(t - 1) * H_DIM);
            uint4 ua, ub;
            do { ua = ld_vol_u4(hp + tid); } while (has_sent(ua));
            do { ub = ld_vol_u4(hp + tid + RNN_THREADS); } while (has_sent(ub));
            a4 = make_float4(__uint_as_float(ua.x), __uint_as_float(ua.y),
                             __uint_as_float(ua.z), __uint_as_float(ua.w));
            b4 = make_float4(__uint_as_float(ub.x), __uint_as_float(ub.y),
                             __uint_as_float(ub.z), __uint_as_float(ub.w));
        }

        // Stage into this step's buffer. No bar needed before the store:
        // previous readers of hbuf[buf] (iteration t-2) are separated from
        // this write by the barriers of iteration t-1.
        ((float4*)hbuf[buf])[tid]               = a4;
        ((float4*)hbuf[buf])[tid + RNN_THREADS] = b4;
        __syncthreads();                          // staging visible

        // Compute partials: 16 rows x 8 k-elems per lane, f32x2 packed.
        unsigned long long acc2[16];
#pragma unroll
        for (int r = 0; r < 16; r++) acc2[r] = 0ull;
#pragma unroll
        for (int p = 0; p < 2; p++) {
            ulonglong2 h2 = ((const ulonglong2*)hbuf[buf])[wid * 64 + p * 32 + lane];
#pragma unroll
            for (int r = 0; r < 16; r++) {
                fma2(acc2[r], wp[r][p].x, h2.x);
                fma2(acc2[r], wp[r][p].y, h2.y);
            }
        }

        // Horizontal add + write partials (16 STS.32, conflict-free: col=tid).
#pragma unroll
        for (int r = 0; r < 16; r++) {
            float2 pr = unpack2(acc2[r]);
            pbuf[r][tid] = pr.x + pr.y;
        }
        __syncthreads();                          // partials visible

        // Final reduce: warp w reduces rows 2w and 2w+1 over 256 partials.
        float s0 = 0.f, s1 = 0.f;
#pragma unroll
        for (int k = 0; k < 8; k++) {
            s0 += pbuf[2 * wid][lane + 32 * k];
            s1 += pbuf[2 * wid + 1][lane + 32 * k];
        }
#pragma unroll
        for (int off = 16; off > 0; off >>= 1) {
            s0 += __shfl_down_sync(0xffffffffu, s0, off);
            s1 += __shfl_down_sync(0xffffffffu, s1, off);
        }

        // Publish h_t: volatile word stores, self-announcing (R8 protocol).
        if (lane == 0) {
            st_vol_f32(&g_hs[(size_t)t * H_DIM + rowbase + 2 * wid],     tanhf(xpv0 + s0));
            st_vol_f32(&g_hs[(size_t)t * H_DIM + rowbase + 2 * wid + 1], tanhf(xpv1 + s1));
        }
        // pbuf reuse next iteration is guarded by next iteration's first bar.
    }
}

// ---------------- tiled fp32 NT GEMM: C[M,N] = A[M,K] @ B[N,K]^T + bias --
// f32x2 packed along M (A-pairs natural from smem; per-acc FFMA sequence is
// unchanged -> bit-identical results to the scalar version).
// PHASE 0: A = param (x),   C = g_xp,  bias = b_ih + b_hh
// PHASE 1: A = g_hs,        C = param, bias = b_lin
#define BM 128
#define BN 64
#define BK 16

template<int PHASE>
__global__ void __launch_bounds__(256, 3)
gemm_nt_bias(const float* __restrict__ A_param,
             const float* __restrict__ B,
             const float* __restrict__ bias1,
             const float* __restrict__ bias2,
             float* __restrict__ C_param,
             int M, int N, int K)
{
    __shared__ __align__(16) float As[BK][BM + 4];
    __shared__ __align__(16) float Bs[BK][BN + 4];

    const float* A = (PHASE == 0) ? A_param : g_hs;
    float*       C = (PHASE == 0) ? g_xp    : C_param;

    const int tid = threadIdx.x;
    const int m0  = blockIdx.y * BM;
    const int n0  = blockIdx.x * BN;
    const int ty  = tid >> 4;    // 0..15 -> rows ty*8..+7
    const int tx  = tid & 15;    // 0..15 -> cols tx*4..+3

    // accp[i2][j] packs rows (2*i2, 2*i2+1) for column j.
    unsigned long long accp[4][4];
#pragma unroll
    for (int i = 0; i < 4; i++)
#pragma unroll
        for (int j = 0; j < 4; j++) accp[i][j] = 0ull;

    for (int k0 = 0; k0 < K; k0 += BK) {
        // A tile: 128x16 = 512 float4, 2 per thread
#pragma unroll
        for (int it = 0; it < 2; it++) {
            int idx = tid + it * 256;
            int row = idx >> 2, kq = idx & 3;
            float4 v = *(const float4*)(A + (size_t)(m0 + row) * K + k0 + kq * 4);
            As[kq * 4 + 0][row] = v.x;
            As[kq * 4 + 1][row] = v.y;
            As[kq * 4 + 2][row] = v.z;
            As[kq * 4 + 3][row] = v.w;
        }
        // B tile: 64x16 = 256 float4, 1 per thread
        {
            int row = tid >> 2, kq = tid & 3;
            float4 v = *(const float4*)(B + (size_t)(n0 + row) * K + k0 + kq * 4);
            Bs[kq * 4 + 0][row] = v.x;
            Bs[kq * 4 + 1][row] = v.y;
            Bs[kq * 4 + 2][row] = v.z;
            Bs[kq * 4 + 3][row] = v.w;
        }
        __syncthreads();

#pragma unroll
        for (int kk = 0; kk < BK; kk++) {
            ulonglong2 ap01 = *(const ulonglong2*)&As[kk][ty * 8];      // rows 0..3
            ulonglong2 ap23 = *(const ulonglong2*)&As[kk][ty * 8 + 4];  // rows 4..7
            float4 bv = *(const float4*)&Bs[kk][tx * 4];
            unsigned long long bd[4];
            bd[0] = pack2(bv.x, bv.x);
            bd[1] = pack2(bv.y, bv.y);
            bd[2] = pack2(bv.z, bv.z);
            bd[3] = pack2(bv.w, bv.w);
#pragma unroll
            for (int j = 0; j < 4; j++) {
                fma2(accp[0][j], ap01.x, bd[j]);
                fma2(accp[1][j], ap01.y, bd[j]);
                fma2(accp[2][j], ap23.x, bd[j]);
                fma2(accp[3][j], ap23.y, bd[j]);
            }
        }
        __syncthreads();
    }

    // epilogue: bias + store
    float bsum[4];
#pragma unroll
    for (int j = 0; j < 4; j++) {
        int n = n0 + tx * 4 + j;
        float bv = __ldg(&bias1[n]);
        if (bias2) bv += __ldg(&bias2[n]);
        bsum[j] = bv;
    }
#pragma unroll
    for (int i2 = 0; i2 < 4; i2++) {
        float4 o0, o1;
        float2 c0 = unpack2(accp[i2][0]);
        float2 c1 = unpack2(accp[i2][1]);
        float2 c2 = unpack2(accp[i2][2]);
        float2 c3 = unpack2(accp[i2][3]);
        o0.x = c0.x + bsum[0]; o0.y = c1.x + bsum[1];
        o0.z = c2.x + bsum[2]; o0.w = c3.x + bsum[3];
        o1.x = c0.y + bsum[0]; o1.y = c1.y + bsum[1];
        o1.z = c2.y + bsum[2]; o1.w = c3.y + bsum[3];
        *(float4*)(C + (size_t)(m0 + ty * 8 + 2 * i2) * N + n0 + tx * 4)     = o0;
        *(float4*)(C + (size_t)(m0 + ty * 8 + 2 * i2 + 1) * N + n0 + tx * 4) = o1;
    }
}

// ---------------- launch ------------------------------------------------
extern "C" void kernel_launch(void* const* d_in, const int* in_sizes, int n_in,
                              void* d_out, int out_size)
{
    const float* x     = (const float*)d_in[0];  // (T,1,H)
    const float* W_ih  = (const float*)d_in[1];  // (H,H)
    const float* W_hh  = (const float*)d_in[2];  // (H,H)
    const float* b_ih  = (const float*)d_in[3];  // (H)
    const float* b_hh  = (const float*)d_in[4];  // (H)
    const float* W_lin = (const float*)d_in[5];  // (O,H)
    const float* b_lin = (const float*)d_in[6];  // (O)
    const float* h0    = (const float*)d_in[7];  // (1,1,H)
    float* out = (float*)d_out;                  // (T,1,O)

    // Reset g_hs to sentinel (must precede rnn_kernel every launch/replay).
    reset_hs_kernel<<<(T_STEPS * H_DIM / 4) / 256, 256>>>();

    // Phase 1: g_xp = x @ W_ih^T + b_ih + b_hh
    gemm_nt_bias<0><<<dim3(H_DIM / BN, T_STEPS / BM), 256>>>(
        x, W_ih, b_ih, b_hh, nullptr, T_STEPS, H_DIM, H_DIM);

    // Phase 2: sequential recurrence -> g_hs
    rnn_kernel<<<RNN_CTAS, RNN_THREADS>>>(W_hh, h0);

    // Phase 3: out = g_hs @ W_lin^T + b_lin
    gemm_nt_bias<1><<<dim3(O_DIM / BN, T_STEPS / BM), 256>>>(
        nullptr, W_lin, b_lin, nullptr, out, T_STEPS, O_DIM, H_DIM);
}